// round 2
// baseline (speedup 1.0000x reference)
#include <cuda_runtime.h>
#include <cuda_bf16.h>

// Closed-form Heisenberg-picture evaluation of the 4-qubit circuit.
// Per sample: Cq = cos(pi*x_q), Sq = sin(pi*x_q).
//   ev0 = cos(w2)*cos(w0)*C0 - sin(w2)*S0*S2
//   ev1 = cos(w1)*C1
//   ev2 = cos(w0)*C0*C2
//   ev3 = cos(w3)*cos(w0)*C0*C2*C3 - sin(w3)*S3
// Purely memory-bound: 16B in + 16B out per sample.

__global__ __launch_bounds__(256) void quanv_closed_kernel(
    const float4* __restrict__ x,
    const float* __restrict__ w,
    float4* __restrict__ out,
    int B)
{
    int i = blockIdx.x * blockDim.x + threadIdx.x;
    if (i >= B) return;

    // Weight trig (uniform across threads; L1/const-cache broadcast).
    float cw0, sw0_unused, cw1, cw2, sw2, cw3, sw3, dummy;
    __sincosf(__ldg(w + 0), &sw0_unused, &cw0);
    __sincosf(__ldg(w + 1), &dummy, &cw1);
    __sincosf(__ldg(w + 2), &sw2, &cw2);
    __sincosf(__ldg(w + 3), &sw3, &cw3);

    float4 xv = __ldg(x + i);

    const float PI = 3.14159265358979323846f;
    float C0, S0, C1, C2, S2, C3, S3, tmp;
    __sincosf(xv.x * PI, &S0, &C0);
    __sincosf(xv.y * PI, &tmp, &C1);
    __sincosf(xv.z * PI, &S2, &C2);
    __sincosf(xv.w * PI, &S3, &C3);

    float a   = cw0 * C0;          // cos(w0)*C0
    float ev1 = cw1 * C1;
    float ev2 = a * C2;
    float ev0 = cw2 * a - sw2 * (S0 * S2);
    float ev3 = cw3 * (ev2 * C3) - sw3 * S3;

    out[i] = make_float4(ev0, ev1, ev2, ev3);
}

extern "C" void kernel_launch(void* const* d_in, const int* in_sizes, int n_in,
                              void* d_out, int out_size) {
    const float4* x = (const float4*)d_in[0];   // [B, 4] float32
    const float* w  = (const float*)d_in[1];    // [4] float32
    float4* out     = (float4*)d_out;           // [B, 4] float32

    int B = in_sizes[0] / 4;
    int threads = 256;
    int blocks = (B + threads - 1) / threads;
    quanv_closed_kernel<<<blocks, threads>>>(x, w, out, B);
}